// round 14
// baseline (speedup 1.0000x reference)
#include <cuda_runtime.h>
#include <math_constants.h>

#define BATCH 262144
#define NLAYER 8
#define H 128
#define NSEG 129
#define BN_EPS 1e-5f
#define FLOW_EPS 1e-4f
#define INVALID 0xFFFFFFFFu
#define NREP 4
#define NB 148
#define NT 1024

// ---------------- device scratch (no allocs allowed) ----------------
__device__ unsigned g_arrive = 0, g_release = 0;   // grid barrier (monotonic, replay-safe)
__device__ double g_sum[2][2];                     // [parity][s,q]
__device__ int    g_cntR[2][NREP][NSEG];
__device__ float  g_s1R[2][NREP][NSEG], g_s2R[2][NREP][NSEG];
__device__ __align__(16) float g_tab[NSEG * H * 2];   // level-1 table (A,B per m,j)
__device__ __align__(8) float2 g_ghbh[H];             // BN2 fold factors
__device__ int    g_cursor[2][NSEG];
__device__ int    g_ptotal;
__device__ unsigned g_perm[BATCH + NSEG * 32];
__device__ unsigned char g_mseg[BATCH];
__device__ float g_x[2 * BATCH];
__device__ float g_sldj[BATCH];

// grid-wide barrier: all NB blocks resident by construction
__device__ __forceinline__ void gridbar()
{
    __syncthreads();
    if (threadIdx.x == 0) {
        unsigned old = *(volatile unsigned*)&g_release;
        __threadfence();
        if (atomicAdd(&g_arrive, 1) == NB - 1) {
            atomicExch(&g_arrive, 0);
            __threadfence();
            atomicExch(&g_release, old + 1);
        } else {
            while (*(volatile unsigned*)&g_release == old) __nanosleep(32);
        }
        __threadfence();
    }
    __syncthreads();
}

// shared layout (float offsets) in the X region after the float4 table area
#define XO_SA    0
#define XO_SC    128
#define XO_STHR  256
#define XO_STHS  384
#define XO_SORD  512
#define XO_SVR   640
#define XO_SCNT  768        // int[129]
#define XO_SS1   900        // hist floats / P3 bcnt ints
#define XO_SS2   1032       // hist floats / P3 bbase ints
#define XO_EOFF  1164       // int[130]
#define XO_GHBH  1296       // float[256]
#define XO_WS    1552       // warp partials (48)
#define XO_MISC  1600       // 8
#define XO_EF    1608       // float4[NSEG] per-segment (E0,F0,E1,F1) = 516 floats
#define X_FLOATS 2128
#define SMEM_ALL ((NSEG * 64 + 64) * 16 + X_FLOATS * 4)

__global__ void __launch_bounds__(NT, 1) k_all(
    const float* __restrict__ x,
    const float* __restrict__ v1,  const float* __restrict__ g1,  const float* __restrict__ b1,
    const float* __restrict__ bn1g,const float* __restrict__ bn1b,
    const float* __restrict__ v2,  const float* __restrict__ g2,  const float* __restrict__ b2,
    const float* __restrict__ bn2g,const float* __restrict__ bn2b,
    const float* __restrict__ wf,  const float* __restrict__ bf,
    float* __restrict__ out)
{
    extern __shared__ float sm[];
    float4* stab4 = (float4*)sm;                 // NSEG*64 float4 table (a0,b0,a1,b1)
    float4* wf4   = stab4 + NSEG * 64;           // 64 float4: (w0_j0,w0_j1,w1_j0,w1_j1)/2
    float*  X     = (float*)(wf4 + 64);

    const int t = threadIdx.x, b = blockIdx.x;
    const int lane = t & 31, wid = t >> 5;

    // ================= P0: copy x, stats of x[:,1] into g_sum[0] =================
    {
        float kS = 0.f, cS = 0.f, kQ = 0.f, cQ = 0.f;
        for (int i = b * NT + t; i < BATCH; i += NB * NT) {
            float2 p = ((const float2*)x)[i];
            __stcg(((float2*)g_x) + i, p);
            float v = p.y;
            { float yk = v - cS; float tk = kS + yk; cS = (tk - kS) - yk; kS = tk; }
            float v2s = v * v;
            { float yk = v2s - cQ; float tk = kQ + yk; cQ = (tk - kQ) - yk; kQ = tk; }
        }
        double s = (double)kS, q = (double)kQ;
        for (int off = 16; off; off >>= 1) {
            s += __shfl_down_sync(0xffffffffu, s, off);
            q += __shfl_down_sync(0xffffffffu, q, off);
        }
        __shared__ double ss[32], sq[32];
        if (!lane) { ss[wid] = s; sq[wid] = q; }
        __syncthreads();
        if (!wid) {
            s = (lane < NT / 32) ? ss[lane] : 0.0;
            q = (lane < NT / 32) ? sq[lane] : 0.0;
            for (int off = 16; off; off >>= 1) {
                s += __shfl_down_sync(0xffffffffu, s, off);
                q += __shfl_down_sync(0xffffffffu, q, off);
            }
            if (!lane) { atomicAdd(&g_sum[0][0], s); atomicAdd(&g_sum[0][1], q); }
        }
        if (b == 1) {   // parity-0 buffers zero at start of each replay (idempotent)
            for (int idx = t; idx < NREP * NSEG; idx += NT) {
                ((int*)g_cntR[0])[idx] = 0;
                ((float*)g_s1R[0])[idx] = 0.f;
                ((float*)g_s2R[0])[idx] = 0.f;
            }
            for (int idx = t; idx < NSEG; idx += NT) g_cursor[0][idx] = 0;
        }
    }
    gridbar();

    for (int l = 0; l < NLAYER; l++) {
        const int par = l & 1, nxt = par ^ 1;
        const int uIdx = (l & 1) ^ 1, oIdx = 1 - uIdx;
        const int isLast = (l == NLAYER - 1);

        float* sa = X + XO_SA; float* sc = X + XO_SC; float* sthr = X + XO_STHR;
        float* sths = X + XO_STHS; int* sord = (int*)(X + XO_SORD); float* svr = X + XO_SVR;
        int* scnt = (int*)(X + XO_SCNT); float* ss1 = X + XO_SS1; float* ss2 = X + XO_SS2;
        float* WS = X + XO_WS; float* miscf = X + XO_MISC;

        // ================= P1: BN1 fold + lvl1 sort + lvl1 table build + hist =================
        if (t < H) {
            double mu = __ldcg(&g_sum[par][0]) * (1.0 / BATCH);
            double qq = __ldcg(&g_sum[par][1]) * (1.0 / BATCH);
            double var = qq - mu * mu;
            float meanu = (float)mu;
            float varu = (float)(var < 0.0 ? 0.0 : var);
            float v  = v1[l * H + t];
            float w1 = g1[l * H + t] * (v / fabsf(v));
            float r  = rsqrtf(w1 * w1 * varu + BN_EPS);
            float a  = w1 * bn1g[l * H + t] * r;
            float c  = bn1b[l * H + t] - a * meanu;
            sa[t] = a; sc[t] = c;
            sthr[t] = (a != 0.f) ? (-c / a) : CUDART_INF_F;
        }
        __syncthreads();
        if (t < H) {
            float th = sthr[t];
            int rank = 0;
            for (int j2 = 0; j2 < H; j2++) {
                float tj = sthr[j2];
                rank += (tj < th) || (tj == th && j2 < t);
            }
            sths[rank] = th; sord[rank] = t;
        }
        if (b == NB - 1) {  // zero next-parity buffers + next g_sum + next cursors
            for (int idx = t; idx < NREP * NSEG; idx += NT) {
                ((int*)g_cntR[nxt])[idx] = 0;
                ((float*)g_s1R[nxt])[idx] = 0.f;
                ((float*)g_s2R[nxt])[idx] = 0.f;
            }
            for (int idx = t; idx < NSEG; idx += NT) g_cursor[nxt][idx] = 0;
            if (t == 0) { g_sum[nxt][0] = 0.0; g_sum[nxt][1] = 0.0; }
        }
        __syncthreads();

        if (b < H) {  // build level-1 column j=b: register shfl reduce + scan
            const int j = b;
            if (t < H) svr[t] = v2[l * H * H + j * H + t];
            __syncthreads();
            float nv = (t < H) ? svr[t] * svr[t] : 0.f;
#pragma unroll
            for (int o = 16; o; o >>= 1) nv += __shfl_xor_sync(0xffffffffu, nv, o);
            if (lane == 0 && wid < 8) WS[wid] = nv;
            __syncthreads();
            if (t == 0) miscf[0] = g2[l * H + j] / sqrtf(WS[0] + WS[1] + WS[2] + WS[3]);
            __syncthreads();
            float wsc = miscf[0];

            float bA = 0.f, bB = 0.f;
            if (t < H) {
                float aa = sa[t], cc = sc[t], w = wsc * svr[t];
                if (aa < 0.f)                     { bA = w * aa; bB = w * cc; }
                else if (aa == 0.f && cc > 0.f)   { bB = w * cc; }
            }
            float dA = 0.f, dB = 0.f;
            if (t >= 1 && t <= H) {
                int kk = sord[t - 1];
                float aa = sa[kk], cc = sc[kk], w = wsc * svr[kk];
                float sgn = (aa > 0.f) ? 1.f : ((aa < 0.f) ? -1.f : 0.f);
                dA = sgn * w * aa; dB = sgn * w * cc;
            }
            float rA = bA, rB = bB;
#pragma unroll
            for (int o = 16; o; o >>= 1) {
                rA += __shfl_xor_sync(0xffffffffu, rA, o);
                rB += __shfl_xor_sync(0xffffffffu, rB, o);
            }
            if (lane == 0 && wid < 8) { WS[0 + wid] = rA; WS[8 + wid] = rB; }
            float sA = dA, sB = dB;
#pragma unroll
            for (int o = 1; o < 32; o <<= 1) {
                float uA = __shfl_up_sync(0xffffffffu, sA, o);
                float uB = __shfl_up_sync(0xffffffffu, sB, o);
                if (lane >= o) { sA += uA; sB += uB; }
            }
            if (lane == 31 && wid < 8) { WS[16 + wid] = sA; WS[24 + wid] = sB; }
            __syncthreads();
            if (t == 0) {
                miscf[1] = WS[0] + WS[1] + WS[2] + WS[3];
                miscf[2] = WS[8] + WS[9] + WS[10] + WS[11] + b2[l * H + j];
                float accA = 0.f, accB = 0.f;
#pragma unroll
                for (int w2 = 0; w2 < 5; w2++) {
                    WS[32 + w2] = accA; WS[40 + w2] = accB;
                    accA += WS[16 + w2]; accB += WS[24 + w2];
                }
            }
            __syncthreads();
            if (t <= H) {
                float2 val = make_float2(miscf[1] + WS[32 + wid] + sA,
                                         miscf[2] + WS[40 + wid] + sB);
                __stcg(((float2*)g_tab) + t * H + j, val);
            }
        }
        __syncthreads();

        // hist: register-accumulated hot tails (0 and H), smem atomics for interior
        for (int i = t; i < NSEG; i += NT) { scnt[i] = 0; ss1[i] = 0.f; ss2[i] = 0.f; }
        __syncthreads();
        {
            float as1l = 0.f, as2l = 0.f, as1h = 0.f, as2h = 0.f;
            int acl = 0, ach = 0;
            for (int i = b * NT + t; i < BATCH; i += NB * NT) {
                float2 p = __ldcg(((const float2*)g_x) + i);
                float u = uIdx ? p.y : p.x;
                int m = 0;
#pragma unroll
                for (int s = 64; s >= 1; s >>= 1) { int nm = m + s; if (sths[nm - 1] < u) m = nm; }
                if (sths[H - 1] < u) m = H;   // 7-step count saturates at 127
                __stcg(&g_mseg[i], (unsigned char)m);
                float u2 = u * u;
                if (m == 0)      { as1l += u; as2l += u2; acl++; }
                else if (m == H) { as1h += u; as2h += u2; ach++; }
                else {
                    atomicAdd(&scnt[m], 1);
                    atomicAdd(&ss1[m], u);
                    atomicAdd(&ss2[m], u2);
                }
            }
#pragma unroll
            for (int o = 16; o; o >>= 1) {
                as1l += __shfl_xor_sync(0xffffffffu, as1l, o);
                as2l += __shfl_xor_sync(0xffffffffu, as2l, o);
                as1h += __shfl_xor_sync(0xffffffffu, as1h, o);
                as2h += __shfl_xor_sync(0xffffffffu, as2h, o);
                acl  += __shfl_xor_sync(0xffffffffu, acl, o);
                ach  += __shfl_xor_sync(0xffffffffu, ach, o);
            }
            if (lane == 0) {
                if (acl) { atomicAdd(&scnt[0], acl); atomicAdd(&ss1[0], as1l); atomicAdd(&ss2[0], as2l); }
                if (ach) { atomicAdd(&scnt[H], ach); atomicAdd(&ss1[H], as1h); atomicAdd(&ss2[H], as2h); }
            }
        }
        __syncthreads();
        {
            int r = b & (NREP - 1);
            for (int i = t; i < NSEG; i += NT) {
                if (scnt[i]) {
                    atomicAdd(&g_cntR[par][r][i], scnt[i]);
                    atomicAdd(&g_s1R[par][r][i], ss1[i]);
                    atomicAdd(&g_s2R[par][r][i], ss2[i]);
                }
            }
        }
        gridbar();

        // ================= P3: offsets + scatter + ghbh (hidden behind scatter) ============
        {
            int* ecnt = (int*)(X + XO_SCNT);
            int* eoff = (int*)(X + XO_EOFF);
            int* bcnt = (int*)(X + XO_SS1);
            int* bbase = (int*)(X + XO_SS2);
            if (t < NSEG) {
                int c = 0;
#pragma unroll
                for (int r = 0; r < NREP; r++) c += __ldcg(&g_cntR[par][r][t]);
                ecnt[t] = c;
            }
            for (int i = t; i < NSEG; i += NT) bcnt[i] = 0;
            __syncthreads();
            if (t == 0) {
                int run = 0;
                for (int s = 0; s < NSEG; s++) { eoff[s] = run; run += (ecnt[s] + 31) & ~31; }
                eoff[NSEG] = run;
                if (b == 0) g_ptotal = run;
            }
            __syncthreads();
            int m0s = 0, m1s = 0, r0s = 0, r1s = 0, i0 = 0, i1 = 0;
            if (b < H) {
                i0 = b * 2048 + t; i1 = i0 + 1024;
                m0s = __ldcg(&g_mseg[i0]);
                m1s = __ldcg(&g_mseg[i1]);
                r0s = atomicAdd(&bcnt[m0s], 1);
                r1s = atomicAdd(&bcnt[m1s], 1);
            }
            __syncthreads();
            if (b < H && t < NSEG)
                bbase[t] = bcnt[t] ? atomicAdd(&g_cursor[par][t], bcnt[t]) : 0;
            __syncthreads();
            if (b < H) {
                __stcg(&g_perm[eoff[m0s] + bbase[m0s] + r0s], ((unsigned)m0s << 18) | (unsigned)i0);
                __stcg(&g_perm[eoff[m1s] + bbase[m1s] + r1s], ((unsigned)m1s << 18) | (unsigned)i1);
            }
            if (b < NSEG) {
                for (int p = eoff[b] + ecnt[b] + t; p < eoff[b + 1]; p += NT)
                    __stcg(&g_perm[p], INVALID);
            }
            // ghbh[j=b]: one term per thread (segment m=t), shfl reduce
            if (b < H) {
                const int j = b;
                float t1 = 0.f, t2 = 0.f;
                if (t < NSEG) {
                    float S1 = 0.f, S2 = 0.f;
#pragma unroll
                    for (int r = 0; r < NREP; r++) {
                        S1 += __ldcg(&g_s1R[par][r][t]);
                        S2 += __ldcg(&g_s2R[par][r][t]);
                    }
                    float N = (float)ecnt[t];
                    float2 ab = __ldcg(((const float2*)g_tab) + t * H + j);
                    t1 = ab.x * S1 + ab.y * N;
                    t2 = ab.x * (ab.x * S2 + 2.f * ab.y * S1) + ab.y * ab.y * N;
                }
#pragma unroll
                for (int o = 16; o; o >>= 1) {
                    t1 += __shfl_xor_sync(0xffffffffu, t1, o);
                    t2 += __shfl_xor_sync(0xffffffffu, t2, o);
                }
                if (lane == 0 && wid < 8) { WS[0 + wid] = t1; WS[8 + wid] = t2; }
                __syncthreads();
                if (t == 0) {
                    float m1 = WS[0] + WS[1] + WS[2] + WS[3] + WS[4];
                    float m2 = WS[8] + WS[9] + WS[10] + WS[11] + WS[12];
                    float mean = m1 * (1.f / BATCH);
                    float var  = m2 * (1.f / BATCH) - mean * mean;
                    if (var < 0.f) var = 0.f;
                    float gh = bn2g[l * H + j] * rsqrtf(var + BN_EPS);
                    float bh = bn2b[l * H + j] - gh * mean;
                    __stcg(&g_ghbh[j], make_float2(gh, bh));
                }
            }
        }
        gridbar();

        // ================= P4: fused table fold-load + per-segment E/F, then apply =========
        {
            float* ghbhS = X + XO_GHBH;
            float* sEF   = X + XO_EF;   // [m*4 + {E0,F0,E1,F1}]
            if (t < 2 * H) ghbhS[t] = __ldcg(((const float*)g_ghbh) + t);
            for (int i = t; i < NSEG * 4; i += NT) sEF[i] = 0.f;
            for (int jj = t; jj < 64; jj += NT) {
                int j0 = 2 * jj, j1 = 2 * jj + 1;
                // halved weights: (w0_j0, w0_j1, w1_j0, w1_j1)/2
                wf4[jj] = make_float4(0.5f * wf[(l * 2 + 0) * H + j0], 0.5f * wf[(l * 2 + 0) * H + j1],
                                      0.5f * wf[(l * 2 + 1) * H + j0], 0.5f * wf[(l * 2 + 1) * H + j1]);
            }
            __syncthreads();
            for (int idx = t; idx < NSEG * 64; idx += NT) {
                float4 tv = __ldcg(((const float4*)g_tab) + idx);   // (A0,B0,A1,B1)
                int jj = idx & 63;
                float g0 = ghbhS[4 * jj], b0 = ghbhS[4 * jj + 1];
                float g1v = ghbhS[4 * jj + 2], b1v = ghbhS[4 * jj + 3];
                float a0 = g0 * tv.x,  bb0 = fmaf(g0, tv.y, b0);
                float a1 = g1v * tv.z, bb1 = fmaf(g1v, tv.w, b1v);
                stab4[idx] = make_float4(a0, bb0, a1, bb1);
                // E/F partials (half weights)
                float4 w4 = wf4[jj];
                float e0p = fmaf(a0,  w4.x, a1  * w4.y);
                float f0p = fmaf(bb0, w4.x, bb1 * w4.y);
                float e1p = fmaf(a0,  w4.z, a1  * w4.w);
                float f1p = fmaf(bb0, w4.z, bb1 * w4.w);
#pragma unroll
                for (int o = 16; o; o >>= 1) {
                    e0p += __shfl_xor_sync(0xffffffffu, e0p, o);
                    f0p += __shfl_xor_sync(0xffffffffu, f0p, o);
                    e1p += __shfl_xor_sync(0xffffffffu, e1p, o);
                    f1p += __shfl_xor_sync(0xffffffffu, f1p, o);
                }
                if (lane == 0) {   // 32-idx chunk is warp-uniform in m (never crosses 64-boundary)
                    int m = idx >> 6;
                    atomicAdd(&sEF[m * 4 + 0], e0p);
                    atomicAdd(&sEF[m * 4 + 1], f0p);
                    atomicAdd(&sEF[m * 4 + 2], e1p);
                    atomicAdd(&sEF[m * 4 + 3], f1p);
                }
            }
            __syncthreads();

            const int P = __ldcg(&g_ptotal);
            float bf0 = bf[l * 2], bf1 = bf[l * 2 + 1];
            float kS = 0.f, cS = 0.f, kQ = 0.f, cQ = 0.f;
            int gw = b * 32 + wid, nw = NB * 32;

            for (int base = gw * 32; base < P; base += nw * 32) {
                unsigned pv  = __ldcg(&g_perm[base + lane]);
                unsigned pv0 = __shfl_sync(0xffffffffu, pv, 0);   // lane 0 valid (32-aligned)
                int m0 = (int)(pv0 >> 18);
                bool valid = (pv != INVALID);
                unsigned i = valid ? (pv & 0x3FFFFu) : 0u;

                float2 p = __ldcg(((const float2*)g_x) + i);
                float u  = uIdx ? p.y : p.x;
                float xo = uIdx ? p.x : p.y;

                const float4* row = stab4 + m0 * 64;
                float4 EF = ((const float4*)sEF)[m0];   // broadcast
                float st0a = 0.f, st1a = 0.f, st0b = 0.f, st1b = 0.f;
#pragma unroll 8
                for (int c = 0; c < 64; c += 2) {
                    float4 tv = row[c];     float4 w4 = wf4[c];
                    float v0 = fmaf(tv.x, u, tv.y);
                    float v1 = fmaf(tv.z, u, tv.w);
                    st0a = fmaf(fabsf(v0), w4.x, st0a);
                    st0b = fmaf(fabsf(v1), w4.y, st0b);
                    st1a = fmaf(fabsf(v0), w4.z, st1a);
                    st1b = fmaf(fabsf(v1), w4.w, st1b);
                    float4 tv2 = row[c + 1]; float4 w42 = wf4[c + 1];
                    float v2 = fmaf(tv2.x, u, tv2.y);
                    float v3 = fmaf(tv2.z, u, tv2.w);
                    st0a = fmaf(fabsf(v2), w42.x, st0a);
                    st0b = fmaf(fabsf(v3), w42.y, st0b);
                    st1a = fmaf(fabsf(v2), w42.z, st1a);
                    st1b = fmaf(fabsf(v3), w42.w, st1b);
                }
                float st0 = fmaf(EF.x, u, EF.y) + bf0 + st0a + st0b;
                float st1 = fmaf(EF.z, u, EF.w) + bf1 + st1a + st1b;
                float e2  = __expf(2.f * st0);
                float sv  = 1.f - 2.f * __fdividef(1.f, e2 + 1.f);   // tanh
                float y   = fmaf(__expf(sv), xo, st1);

                if (valid) {
                    float sld = (l == 0 ? 0.f : __ldcg(&g_sldj[i])) + sv;
                    if (!isLast) {
                        __stcg(&g_x[2 * i + oIdx], y);
                        __stcg(&g_sldj[i], sld);
                        { float yk = y - cS;  float tk = kS + yk; cS = (tk - kS) - yk; kS = tk; }
                        float yy = y * y;
                        { float yk = yy - cQ; float tk = kQ + yk; cQ = (tk - kQ) - yk; kQ = tk; }
                    } else {
                        float zu = __fdividef(1.f, 1.f + __expf(-u));
                        float zo = __fdividef(1.f, 1.f + __expf(-y));
                        sld += __logf(zu * (1.f - zu) + FLOW_EPS) + __logf(zo * (1.f - zo) + FLOW_EPS);
                        out[2 * i + uIdx] = zu;
                        out[2 * i + oIdx] = zo;
                        out[2 * BATCH + i] = sld;
                    }
                }
            }

            if (!isLast) {
                double s = (double)kS, q = (double)kQ;
                for (int off = 16; off; off >>= 1) {
                    s += __shfl_down_sync(0xffffffffu, s, off);
                    q += __shfl_down_sync(0xffffffffu, q, off);
                }
                __shared__ double rs[32], rq[32];
                if (!lane) { rs[wid] = s; rq[wid] = q; }
                __syncthreads();
                if (!wid) {
                    s = (lane < NT / 32) ? rs[lane] : 0.0;
                    q = (lane < NT / 32) ? rq[lane] : 0.0;
                    for (int off = 16; off; off >>= 1) {
                        s += __shfl_down_sync(0xffffffffu, s, off);
                        q += __shfl_down_sync(0xffffffffu, q, off);
                    }
                    if (!lane) { atomicAdd(&g_sum[nxt][0], s); atomicAdd(&g_sum[nxt][1], q); }
                }
            }
        }
        if (!isLast) gridbar();
    }
}

// ---------------- host launcher ----------------
extern "C" void kernel_launch(void* const* d_in, const int* in_sizes, int n_in,
                              void* d_out, int out_size)
{
    const float* x    = (const float*)d_in[0];
    const float* v1   = (const float*)d_in[1];
    const float* g1   = (const float*)d_in[2];
    const float* b1   = (const float*)d_in[3];
    const float* bn1g = (const float*)d_in[4];
    const float* bn1b = (const float*)d_in[5];
    const float* v2   = (const float*)d_in[6];
    const float* g2   = (const float*)d_in[7];
    const float* b2   = (const float*)d_in[8];
    const float* bn2g = (const float*)d_in[9];
    const float* bn2b = (const float*)d_in[10];
    const float* wf   = (const float*)d_in[11];
    const float* bf   = (const float*)d_in[12];
    float* out = (float*)d_out;

    cudaFuncSetAttribute(k_all, cudaFuncAttributeMaxDynamicSharedMemorySize, SMEM_ALL);
    k_all<<<NB, NT, SMEM_ALL>>>(x, v1, g1, b1, bn1g, bn1b, v2, g2, b2,
                                bn2g, bn2b, wf, bf, out);
    (void)in_sizes; (void)n_in; (void)out_size;
}

// round 15
// speedup vs baseline: 1.1595x; 1.1595x over previous
#include <cuda_runtime.h>
#include <math_constants.h>

#define BATCH 262144
#define NLAYER 8
#define H 128
#define NSEG 129
#define BN_EPS 1e-5f
#define FLOW_EPS 1e-4f
#define INVALID 0xFFFFFFFFu
#define NREP 4
#define NB 148
#define NT 1024
#define TAB_BYTES (NSEG * 64 * 16)   // 132096

// ---------------- device scratch (no allocs allowed) ----------------
__device__ unsigned g_arrive = 0, g_release = 0;   // grid barrier (monotonic, replay-safe)
__device__ double g_sum[2][2];                     // [parity][s,q]
__device__ int    g_cntR[2][NREP][NSEG];
__device__ float  g_s1R[2][NREP][NSEG], g_s2R[2][NREP][NSEG];
__device__ __align__(16) float g_tab[NSEG * H * 2];   // raw level-1 table (A,B per m,j)
__device__ __align__(16) float g_tabF[NSEG * H * 2];  // BN2-folded table (a,b per m,j)
__device__ int    g_cursor[2][NSEG];
__device__ int    g_ptotal;
__device__ unsigned g_perm[BATCH + NSEG * 32];
__device__ unsigned char g_mseg[BATCH];
__device__ float g_x[2 * BATCH];
__device__ float g_sldj[BATCH];

// grid-wide barrier: all NB blocks resident by construction
__device__ __forceinline__ void gridbar()
{
    __syncthreads();
    if (threadIdx.x == 0) {
        unsigned old = *(volatile unsigned*)&g_release;
        __threadfence();
        if (atomicAdd(&g_arrive, 1) == NB - 1) {
            atomicExch(&g_arrive, 0);
            __threadfence();
            atomicExch(&g_release, old + 1);
        } else {
            while (*(volatile unsigned*)&g_release == old) __nanosleep(32);
        }
        __threadfence();
    }
    __syncthreads();
}

// shared layout (float offsets) in the X region after the float4 table area
#define XO_SA    0
#define XO_SC    128
#define XO_STHR  256
#define XO_STHS  384
#define XO_SORD  512
#define XO_SVR   640
#define XO_SCNT  768        // int[129]
#define XO_SS1   900        // hist floats / P3 bcnt ints
#define XO_SS2   1032       // hist floats / P3 bbase ints
#define XO_EOFF  1164       // int[130]
#define XO_WS    1552       // warp partials (48)
#define XO_MISC  1600       // 8
#define XO_MBAR  1608       // mbarrier (2 floats, 8B aligned)
#define X_FLOATS 1616
#define SMEM_ALL ((NSEG * 64 + 64) * 16 + X_FLOATS * 4)

__global__ void __launch_bounds__(NT, 1) k_all(
    const float* __restrict__ x,
    const float* __restrict__ v1,  const float* __restrict__ g1,  const float* __restrict__ b1,
    const float* __restrict__ bn1g,const float* __restrict__ bn1b,
    const float* __restrict__ v2,  const float* __restrict__ g2,  const float* __restrict__ b2,
    const float* __restrict__ bn2g,const float* __restrict__ bn2b,
    const float* __restrict__ wf,  const float* __restrict__ bf,
    float* __restrict__ out)
{
    extern __shared__ float sm[];
    float4* stab4 = (float4*)sm;                 // NSEG*64 float4 folded table
    float4* wf4   = stab4 + NSEG * 64;           // 64 float4
    float*  X     = (float*)(wf4 + 64);

    const int t = threadIdx.x, b = blockIdx.x;
    const int lane = t & 31, wid = t >> 5;

    // shared-space addresses for mbarrier + table (for cp.async.bulk)
    unsigned mbar_sa, stab_sa;
    asm("{ .reg .u64 ta; cvta.to.shared.u64 ta, %1; cvt.u32.u64 %0, ta; }"
        : "=r"(mbar_sa) : "l"((void*)(X + XO_MBAR)));
    asm("{ .reg .u64 ta; cvta.to.shared.u64 ta, %1; cvt.u32.u64 %0, ta; }"
        : "=r"(stab_sa) : "l"((void*)stab4));
    unsigned long long tabF_ga;
    asm("cvta.to.global.u64 %0, %1;" : "=l"(tabF_ga) : "l"((void*)g_tabF));

    // ================= P0: copy x, stats of x[:,1] into g_sum[0] =================
    {
        float kS = 0.f, cS = 0.f, kQ = 0.f, cQ = 0.f;
        for (int i = b * NT + t; i < BATCH; i += NB * NT) {
            float2 p = ((const float2*)x)[i];
            __stcg(((float2*)g_x) + i, p);
            float v = p.y;
            { float yk = v - cS; float tk = kS + yk; cS = (tk - kS) - yk; kS = tk; }
            float v2s = v * v;
            { float yk = v2s - cQ; float tk = kQ + yk; cQ = (tk - kQ) - yk; kQ = tk; }
        }
        double s = (double)kS, q = (double)kQ;
        for (int off = 16; off; off >>= 1) {
            s += __shfl_down_sync(0xffffffffu, s, off);
            q += __shfl_down_sync(0xffffffffu, q, off);
        }
        __shared__ double ss[32], sq[32];
        if (!lane) { ss[wid] = s; sq[wid] = q; }
        __syncthreads();
        if (!wid) {
            s = (lane < NT / 32) ? ss[lane] : 0.0;
            q = (lane < NT / 32) ? sq[lane] : 0.0;
            for (int off = 16; off; off >>= 1) {
                s += __shfl_down_sync(0xffffffffu, s, off);
                q += __shfl_down_sync(0xffffffffu, q, off);
            }
            if (!lane) { atomicAdd(&g_sum[0][0], s); atomicAdd(&g_sum[0][1], q); }
        }
        if (b == 1) {   // parity-0 buffers zero at start of each replay (idempotent)
            for (int idx = t; idx < NREP * NSEG; idx += NT) {
                ((int*)g_cntR[0])[idx] = 0;
                ((float*)g_s1R[0])[idx] = 0.f;
                ((float*)g_s2R[0])[idx] = 0.f;
            }
            for (int idx = t; idx < NSEG; idx += NT) g_cursor[0][idx] = 0;
        }
    }
    gridbar();

    for (int l = 0; l < NLAYER; l++) {
        const int par = l & 1, nxt = par ^ 1;
        const int uIdx = (l & 1) ^ 1, oIdx = 1 - uIdx;
        const int isLast = (l == NLAYER - 1);

        float* sa = X + XO_SA; float* sc = X + XO_SC; float* sthr = X + XO_STHR;
        float* sths = X + XO_STHS; int* sord = (int*)(X + XO_SORD); float* svr = X + XO_SVR;
        int* scnt = (int*)(X + XO_SCNT); float* ss1 = X + XO_SS1; float* ss2 = X + XO_SS2;
        float* WS = X + XO_WS; float* miscf = X + XO_MISC;

        // ================= P1: BN1 fold + lvl1 sort + lvl1 table build + hist =================
        if (t < H) {
            double mu = __ldcg(&g_sum[par][0]) * (1.0 / BATCH);
            double qq = __ldcg(&g_sum[par][1]) * (1.0 / BATCH);
            double var = qq - mu * mu;
            float meanu = (float)mu;
            float varu = (float)(var < 0.0 ? 0.0 : var);
            float v  = v1[l * H + t];
            float w1 = g1[l * H + t] * (v / fabsf(v));
            float r  = rsqrtf(w1 * w1 * varu + BN_EPS);
            float a  = w1 * bn1g[l * H + t] * r;
            float c  = bn1b[l * H + t] - a * meanu;
            sa[t] = a; sc[t] = c;
            sthr[t] = (a != 0.f) ? (-c / a) : CUDART_INF_F;
        }
        __syncthreads();
        if (t < H) {
            float th = sthr[t];
            int rank = 0;
            for (int j2 = 0; j2 < H; j2++) {
                float tj = sthr[j2];
                rank += (tj < th) || (tj == th && j2 < t);
            }
            sths[rank] = th; sord[rank] = t;
        }
        if (b == NB - 1) {  // zero next-parity buffers + next g_sum + next cursors
            for (int idx = t; idx < NREP * NSEG; idx += NT) {
                ((int*)g_cntR[nxt])[idx] = 0;
                ((float*)g_s1R[nxt])[idx] = 0.f;
                ((float*)g_s2R[nxt])[idx] = 0.f;
            }
            for (int idx = t; idx < NSEG; idx += NT) g_cursor[nxt][idx] = 0;
            if (t == 0) { g_sum[nxt][0] = 0.0; g_sum[nxt][1] = 0.0; }
        }
        __syncthreads();

        if (b < H) {  // build level-1 column j=b: register shfl reduce + scan
            const int j = b;
            if (t < H) svr[t] = v2[l * H * H + j * H + t];
            __syncthreads();
            float nv = (t < H) ? svr[t] * svr[t] : 0.f;
#pragma unroll
            for (int o = 16; o; o >>= 1) nv += __shfl_xor_sync(0xffffffffu, nv, o);
            if (lane == 0 && wid < 8) WS[wid] = nv;
            __syncthreads();
            if (t == 0) miscf[0] = g2[l * H + j] / sqrtf(WS[0] + WS[1] + WS[2] + WS[3]);
            __syncthreads();
            float wsc = miscf[0];

            float bA = 0.f, bB = 0.f;
            if (t < H) {
                float aa = sa[t], cc = sc[t], w = wsc * svr[t];
                if (aa < 0.f)                     { bA = w * aa; bB = w * cc; }
                else if (aa == 0.f && cc > 0.f)   { bB = w * cc; }
            }
            float dA = 0.f, dB = 0.f;
            if (t >= 1 && t <= H) {
                int kk = sord[t - 1];
                float aa = sa[kk], cc = sc[kk], w = wsc * svr[kk];
                float sgn = (aa > 0.f) ? 1.f : ((aa < 0.f) ? -1.f : 0.f);
                dA = sgn * w * aa; dB = sgn * w * cc;
            }
            float rA = bA, rB = bB;
#pragma unroll
            for (int o = 16; o; o >>= 1) {
                rA += __shfl_xor_sync(0xffffffffu, rA, o);
                rB += __shfl_xor_sync(0xffffffffu, rB, o);
            }
            if (lane == 0 && wid < 8) { WS[0 + wid] = rA; WS[8 + wid] = rB; }
            float sA = dA, sB = dB;
#pragma unroll
            for (int o = 1; o < 32; o <<= 1) {
                float uA = __shfl_up_sync(0xffffffffu, sA, o);
                float uB = __shfl_up_sync(0xffffffffu, sB, o);
                if (lane >= o) { sA += uA; sB += uB; }
            }
            if (lane == 31 && wid < 8) { WS[16 + wid] = sA; WS[24 + wid] = sB; }
            __syncthreads();
            if (t == 0) {
                miscf[1] = WS[0] + WS[1] + WS[2] + WS[3];
                miscf[2] = WS[8] + WS[9] + WS[10] + WS[11] + b2[l * H + j];
                float accA = 0.f, accB = 0.f;
#pragma unroll
                for (int w2 = 0; w2 < 5; w2++) {
                    WS[32 + w2] = accA; WS[40 + w2] = accB;
                    accA += WS[16 + w2]; accB += WS[24 + w2];
                }
            }
            __syncthreads();
            if (t <= H) {
                float2 val = make_float2(miscf[1] + WS[32 + wid] + sA,
                                         miscf[2] + WS[40 + wid] + sB);
                __stcg(((float2*)g_tab) + t * H + j, val);
            }
        }
        __syncthreads();

        // hist: register-accumulated hot tails (0 and H), smem atomics for interior
        for (int i = t; i < NSEG; i += NT) { scnt[i] = 0; ss1[i] = 0.f; ss2[i] = 0.f; }
        __syncthreads();
        {
            float as1l = 0.f, as2l = 0.f, as1h = 0.f, as2h = 0.f;
            int acl = 0, ach = 0;
            for (int i = b * NT + t; i < BATCH; i += NB * NT) {
                float2 p = __ldcg(((const float2*)g_x) + i);
                float u = uIdx ? p.y : p.x;
                int m = 0;
#pragma unroll
                for (int s = 64; s >= 1; s >>= 1) { int nm = m + s; if (sths[nm - 1] < u) m = nm; }
                if (sths[H - 1] < u) m = H;   // 7-step count saturates at 127
                __stcg(&g_mseg[i], (unsigned char)m);
                float u2 = u * u;
                if (m == 0)      { as1l += u; as2l += u2; acl++; }
                else if (m == H) { as1h += u; as2h += u2; ach++; }
                else {
                    atomicAdd(&scnt[m], 1);
                    atomicAdd(&ss1[m], u);
                    atomicAdd(&ss2[m], u2);
                }
            }
#pragma unroll
            for (int o = 16; o; o >>= 1) {
                as1l += __shfl_xor_sync(0xffffffffu, as1l, o);
                as2l += __shfl_xor_sync(0xffffffffu, as2l, o);
                as1h += __shfl_xor_sync(0xffffffffu, as1h, o);
                as2h += __shfl_xor_sync(0xffffffffu, as2h, o);
                acl  += __shfl_xor_sync(0xffffffffu, acl, o);
                ach  += __shfl_xor_sync(0xffffffffu, ach, o);
            }
            if (lane == 0) {
                if (acl) { atomicAdd(&scnt[0], acl); atomicAdd(&ss1[0], as1l); atomicAdd(&ss2[0], as2l); }
                if (ach) { atomicAdd(&scnt[H], ach); atomicAdd(&ss1[H], as1h); atomicAdd(&ss2[H], as2h); }
            }
        }
        __syncthreads();
        {
            int r = b & (NREP - 1);
            for (int i = t; i < NSEG; i += NT) {
                if (scnt[i]) {
                    atomicAdd(&g_cntR[par][r][i], scnt[i]);
                    atomicAdd(&g_s1R[par][r][i], ss1[i]);
                    atomicAdd(&g_s2R[par][r][i], ss2[i]);
                }
            }
        }
        gridbar();

        // ====== P3: offsets + scatter + ghbh + table fold (hidden behind scatter) ======
        {
            int* ecnt = (int*)(X + XO_SCNT);
            int* eoff = (int*)(X + XO_EOFF);
            int* bcnt = (int*)(X + XO_SS1);
            int* bbase = (int*)(X + XO_SS2);
            if (t < NSEG) {
                int c = 0;
#pragma unroll
                for (int r = 0; r < NREP; r++) c += __ldcg(&g_cntR[par][r][t]);
                ecnt[t] = c;
            }
            for (int i = t; i < NSEG; i += NT) bcnt[i] = 0;
            __syncthreads();
            if (t == 0) {
                int run = 0;
                for (int s = 0; s < NSEG; s++) { eoff[s] = run; run += (ecnt[s] + 31) & ~31; }
                eoff[NSEG] = run;
                if (b == 0) g_ptotal = run;
            }
            __syncthreads();
            int m0s = 0, m1s = 0, r0s = 0, r1s = 0, i0 = 0, i1 = 0;
            if (b < H) {
                i0 = b * 2048 + t; i1 = i0 + 1024;
                m0s = __ldcg(&g_mseg[i0]);
                m1s = __ldcg(&g_mseg[i1]);
                r0s = atomicAdd(&bcnt[m0s], 1);
                r1s = atomicAdd(&bcnt[m1s], 1);
            }
            __syncthreads();
            if (b < H && t < NSEG)
                bbase[t] = bcnt[t] ? atomicAdd(&g_cursor[par][t], bcnt[t]) : 0;
            __syncthreads();
            if (b < H) {
                __stcg(&g_perm[eoff[m0s] + bbase[m0s] + r0s], ((unsigned)m0s << 18) | (unsigned)i0);
                __stcg(&g_perm[eoff[m1s] + bbase[m1s] + r1s], ((unsigned)m1s << 18) | (unsigned)i1);
            }
            if (b < NSEG) {
                for (int p = eoff[b] + ecnt[b] + t; p < eoff[b + 1]; p += NT)
                    __stcg(&g_perm[p], INVALID);
            }
            // ghbh[j=b] (shfl reduce) THEN fold column j=b into g_tabF
            if (b < H) {
                const int j = b;
                float t1 = 0.f, t2 = 0.f;
                if (t < NSEG) {
                    float S1 = 0.f, S2 = 0.f;
#pragma unroll
                    for (int r = 0; r < NREP; r++) {
                        S1 += __ldcg(&g_s1R[par][r][t]);
                        S2 += __ldcg(&g_s2R[par][r][t]);
                    }
                    float N = (float)ecnt[t];
                    float2 ab = __ldcg(((const float2*)g_tab) + t * H + j);
                    t1 = ab.x * S1 + ab.y * N;
                    t2 = ab.x * (ab.x * S2 + 2.f * ab.y * S1) + ab.y * ab.y * N;
                }
#pragma unroll
                for (int o = 16; o; o >>= 1) {
                    t1 += __shfl_xor_sync(0xffffffffu, t1, o);
                    t2 += __shfl_xor_sync(0xffffffffu, t2, o);
                }
                if (lane == 0 && wid < 8) { WS[0 + wid] = t1; WS[8 + wid] = t2; }
                __syncthreads();
                if (t == 0) {
                    float m1 = WS[0] + WS[1] + WS[2] + WS[3] + WS[4];
                    float m2 = WS[8] + WS[9] + WS[10] + WS[11] + WS[12];
                    float mean = m1 * (1.f / BATCH);
                    float var  = m2 * (1.f / BATCH) - mean * mean;
                    if (var < 0.f) var = 0.f;
                    float gh = bn2g[l * H + j] * rsqrtf(var + BN_EPS);
                    float bh = bn2b[l * H + j] - gh * mean;
                    miscf[4] = gh; miscf[5] = bh;
                }
                __syncthreads();
                float gh = miscf[4], bh = miscf[5];
                if (t < NSEG) {
                    float2 ab = __ldcg(((const float2*)g_tab) + t * H + j);
                    float2 fv = make_float2(gh * ab.x, fmaf(gh, ab.y, bh));
                    __stcg(((float2*)g_tabF) + t * H + j, fv);
                }
            }
        }
        gridbar();

        // ================= P4: TMA bulk copy folded table -> smem, then apply =========
        {
            if (t == 0) {
                // init mbarrier (count 1), then expect_tx + bulk copy
                asm volatile("mbarrier.init.shared.b64 [%0], 1;" :: "r"(mbar_sa) : "memory");
            }
            __syncthreads();
            if (t == 0) {
                asm volatile("mbarrier.arrive.expect_tx.shared.b64 _, [%0], %1;"
                             :: "r"(mbar_sa), "r"((unsigned)TAB_BYTES) : "memory");
                asm volatile("cp.async.bulk.shared::cta.global.mbarrier::complete_tx::bytes "
                             "[%0], [%1], %2, [%3];"
                             :: "r"(stab_sa), "l"(tabF_ga), "r"((unsigned)TAB_BYTES), "r"(mbar_sa)
                             : "memory");
            }
            // overlap: fill wf4 while the bulk copy is in flight
            for (int jj = t; jj < 64; jj += NT) {
                int j0 = 2 * jj, j1 = 2 * jj + 1;
                wf4[jj] = make_float4(wf[(l * 2 + 0) * H + j0], wf[(l * 2 + 1) * H + j0],
                                      wf[(l * 2 + 0) * H + j1], wf[(l * 2 + 1) * H + j1]);
            }
            // all threads wait for copy completion (parity 0 after fresh init)
            asm volatile(
                "{\n\t.reg .pred p;\n"
                "WAITLP%=:\n\t"
                "mbarrier.try_wait.parity.acquire.cta.shared::cta.b64 p, [%0], 0, 0x989680;\n\t"
                "@!p bra WAITLP%=;\n\t}"
                :: "r"(mbar_sa) : "memory");
            __syncthreads();

            const int P = __ldcg(&g_ptotal);
            float bf0 = bf[l * 2], bf1 = bf[l * 2 + 1];
            float kS = 0.f, cS = 0.f, kQ = 0.f, cQ = 0.f;
            int gw = b * 32 + wid, nw = NB * 32;

            for (int base = gw * 32; base < P; base += nw * 32) {
                unsigned pv  = __ldcg(&g_perm[base + lane]);
                unsigned pv0 = __shfl_sync(0xffffffffu, pv, 0);   // lane 0 valid (32-aligned)
                int m0 = (int)(pv0 >> 18);
                bool valid = (pv != INVALID);
                unsigned i = valid ? (pv & 0x3FFFFu) : 0u;

                float2 p = __ldcg(((const float2*)g_x) + i);
                float u  = uIdx ? p.y : p.x;
                float xo = uIdx ? p.x : p.y;

                const float4* row = stab4 + m0 * 64;
                float st0a = 0.f, st1a = 0.f, st0b = 0.f, st1b = 0.f;
#pragma unroll 8
                for (int c = 0; c < 64; c += 2) {
                    float4 tv = row[c];     float4 w4 = wf4[c];
                    float h0 = fmaxf(fmaf(tv.x, u, tv.y), 0.f);
                    float h1 = fmaxf(fmaf(tv.z, u, tv.w), 0.f);
                    st0a = fmaf(w4.x, h0, fmaf(w4.z, h1, st0a));
                    st1a = fmaf(w4.y, h0, fmaf(w4.w, h1, st1a));
                    float4 tv2 = row[c + 1]; float4 w42 = wf4[c + 1];
                    float h2 = fmaxf(fmaf(tv2.x, u, tv2.y), 0.f);
                    float h3 = fmaxf(fmaf(tv2.z, u, tv2.w), 0.f);
                    st0b = fmaf(w42.x, h2, fmaf(w42.z, h3, st0b));
                    st1b = fmaf(w42.y, h2, fmaf(w42.w, h3, st1b));
                }
                float st0 = st0a + st0b + bf0;
                float st1 = st1a + st1b + bf1;
                float e2  = __expf(2.f * st0);
                float sv  = 1.f - 2.f * __fdividef(1.f, e2 + 1.f);   // tanh
                float y   = fmaf(__expf(sv), xo, st1);

                if (valid) {
                    float sld = (l == 0 ? 0.f : __ldcg(&g_sldj[i])) + sv;
                    if (!isLast) {
                        __stcg(&g_x[2 * i + oIdx], y);
                        __stcg(&g_sldj[i], sld);
                        { float yk = y - cS;  float tk = kS + yk; cS = (tk - kS) - yk; kS = tk; }
                        float yy = y * y;
                        { float yk = yy - cQ; float tk = kQ + yk; cQ = (tk - kQ) - yk; kQ = tk; }
                    } else {
                        float zu = __fdividef(1.f, 1.f + __expf(-u));
                        float zo = __fdividef(1.f, 1.f + __expf(-y));
                        sld += __logf(zu * (1.f - zu) + FLOW_EPS) + __logf(zo * (1.f - zo) + FLOW_EPS);
                        out[2 * i + uIdx] = zu;
                        out[2 * i + oIdx] = zo;
                        out[2 * BATCH + i] = sld;
                    }
                }
            }

            if (!isLast) {
                double s = (double)kS, q = (double)kQ;
                for (int off = 16; off; off >>= 1) {
                    s += __shfl_down_sync(0xffffffffu, s, off);
                    q += __shfl_down_sync(0xffffffffu, q, off);
                }
                __shared__ double rs[32], rq[32];
                if (!lane) { rs[wid] = s; rq[wid] = q; }
                __syncthreads();
                if (!wid) {
                    s = (lane < NT / 32) ? rs[lane] : 0.0;
                    q = (lane < NT / 32) ? rq[lane] : 0.0;
                    for (int off = 16; off; off >>= 1) {
                        s += __shfl_down_sync(0xffffffffu, s, off);
                        q += __shfl_down_sync(0xffffffffu, q, off);
                    }
                    if (!lane) { atomicAdd(&g_sum[nxt][0], s); atomicAdd(&g_sum[nxt][1], q); }
                }
            }
        }
        if (!isLast) gridbar();
    }
}

// ---------------- host launcher ----------------
extern "C" void kernel_launch(void* const* d_in, const int* in_sizes, int n_in,
                              void* d_out, int out_size)
{
    const float* x    = (const float*)d_in[0];
    const float* v1   = (const float*)d_in[1];
    const float* g1   = (const float*)d_in[2];
    const float* b1   = (const float*)d_in[3];
    const float* bn1g = (const float*)d_in[4];
    const float* bn1b = (const float*)d_in[5];
    const float* v2   = (const float*)d_in[6];
    const float* g2   = (const float*)d_in[7];
    const float* b2   = (const float*)d_in[8];
    const float* bn2g = (const float*)d_in[9];
    const float* bn2b = (const float*)d_in[10];
    const float* wf   = (const float*)d_in[11];
    const float* bf   = (const float*)d_in[12];
    float* out = (float*)d_out;

    cudaFuncSetAttribute(k_all, cudaFuncAttributeMaxDynamicSharedMemorySize, SMEM_ALL);
    k_all<<<NB, NT, SMEM_ALL>>>(x, v1, g1, b1, bn1g, bn1b, v2, g2, b2,
                                bn2g, bn2b, wf, bf, out);
    (void)in_sizes; (void)n_in; (void)out_size;
}

// round 16
// speedup vs baseline: 1.1906x; 1.0268x over previous
#include <cuda_runtime.h>
#include <math_constants.h>

#define BATCH 262144
#define NLAYER 8
#define H 128
#define NSEG 129
#define BN_EPS 1e-5f
#define FLOW_EPS 1e-4f
#define INVALID 0xFFFFFFFFu
#define NREP 4
#define NB 148
#define NT 1024
#define TAB_BYTES (NSEG * 64 * 16)   // 132096

// ---------------- device scratch (no allocs allowed) ----------------
__device__ unsigned g_arrive = 0, g_release = 0;   // grid barrier (monotonic, replay-safe)
__device__ double g_sum[2][2];                     // [parity][s,q]
__device__ int    g_cntR[2][NREP][NSEG];
__device__ float  g_s1R[2][NREP][NSEG], g_s2R[2][NREP][NSEG];
__device__ __align__(16) float g_tab[NSEG * H * 2];   // raw level-1 table (A,B per m,j)
__device__ __align__(16) float g_tabF[NSEG * H * 2];  // BN2-folded table (a,b per m,j)
__device__ int    g_cursor[2][NSEG];
__device__ int    g_ptotal;
__device__ unsigned g_perm[BATCH + NSEG * 32];
__device__ unsigned char g_mseg[BATCH];
__device__ __align__(16) float4 g_xs[BATCH];          // (x0, x1, sldj, pad) per sample

// grid-wide barrier: all NB blocks resident by construction
__device__ __forceinline__ void gridbar()
{
    __syncthreads();
    if (threadIdx.x == 0) {
        unsigned old = *(volatile unsigned*)&g_release;
        __threadfence();
        if (atomicAdd(&g_arrive, 1) == NB - 1) {
            atomicExch(&g_arrive, 0);
            __threadfence();
            atomicExch(&g_release, old + 1);
        } else {
            while (*(volatile unsigned*)&g_release == old) __nanosleep(32);
        }
        __threadfence();
    }
    __syncthreads();
}

// shared layout (float offsets) in the X region after the float4 table area
#define XO_SA    0
#define XO_SC    128
#define XO_STHR  256
#define XO_STHS  384
#define XO_SORD  512
#define XO_SVR   640
#define XO_SCNT  768        // int[129]
#define XO_SS1   900        // hist floats / P3 bcnt ints
#define XO_SS2   1032       // hist floats / P3 bbase ints
#define XO_EOFF  1164       // int[130]
#define XO_WS    1552       // warp partials (48)
#define XO_MISC  1600       // 8
#define XO_MBAR  1608       // mbarrier (2 floats, 8B aligned)
#define X_FLOATS 1616
#define SMEM_ALL ((NSEG * 64 + 64) * 16 + X_FLOATS * 4)

__global__ void __launch_bounds__(NT, 1) k_all(
    const float* __restrict__ x,
    const float* __restrict__ v1,  const float* __restrict__ g1,  const float* __restrict__ b1,
    const float* __restrict__ bn1g,const float* __restrict__ bn1b,
    const float* __restrict__ v2,  const float* __restrict__ g2,  const float* __restrict__ b2,
    const float* __restrict__ bn2g,const float* __restrict__ bn2b,
    const float* __restrict__ wf,  const float* __restrict__ bf,
    float* __restrict__ out)
{
    extern __shared__ float sm[];
    float4* stab4 = (float4*)sm;                 // NSEG*64 float4 folded table
    float4* wf4   = stab4 + NSEG * 64;           // 64 float4
    float*  X     = (float*)(wf4 + 64);

    const int t = threadIdx.x, b = blockIdx.x;
    const int lane = t & 31, wid = t >> 5;

    // shared-space addresses for mbarrier + table (for cp.async.bulk)
    unsigned mbar_sa, stab_sa;
    asm("{ .reg .u64 ta; cvta.to.shared.u64 ta, %1; cvt.u32.u64 %0, ta; }"
        : "=r"(mbar_sa) : "l"((void*)(X + XO_MBAR)));
    asm("{ .reg .u64 ta; cvta.to.shared.u64 ta, %1; cvt.u32.u64 %0, ta; }"
        : "=r"(stab_sa) : "l"((void*)stab4));
    unsigned long long tabF_ga;
    asm("cvta.to.global.u64 %0, %1;" : "=l"(tabF_ga) : "l"((void*)g_tabF));

    // ================= P0: build packed records; stats of x[:,1] =================
    {
        float kS = 0.f, cS = 0.f, kQ = 0.f, cQ = 0.f;
        for (int i = b * NT + t; i < BATCH; i += NB * NT) {
            float2 p = ((const float2*)x)[i];
            __stcg(&g_xs[i], make_float4(p.x, p.y, 0.f, 0.f));
            float v = p.y;
            { float yk = v - cS; float tk = kS + yk; cS = (tk - kS) - yk; kS = tk; }
            float v2s = v * v;
            { float yk = v2s - cQ; float tk = kQ + yk; cQ = (tk - kQ) - yk; kQ = tk; }
        }
        double s = (double)kS, q = (double)kQ;
        for (int off = 16; off; off >>= 1) {
            s += __shfl_down_sync(0xffffffffu, s, off);
            q += __shfl_down_sync(0xffffffffu, q, off);
        }
        __shared__ double ss[32], sq[32];
        if (!lane) { ss[wid] = s; sq[wid] = q; }
        __syncthreads();
        if (!wid) {
            s = (lane < NT / 32) ? ss[lane] : 0.0;
            q = (lane < NT / 32) ? sq[lane] : 0.0;
            for (int off = 16; off; off >>= 1) {
                s += __shfl_down_sync(0xffffffffu, s, off);
                q += __shfl_down_sync(0xffffffffu, q, off);
            }
            if (!lane) { atomicAdd(&g_sum[0][0], s); atomicAdd(&g_sum[0][1], q); }
        }
        if (b == 1) {   // parity-0 buffers zero at start of each replay (idempotent)
            for (int idx = t; idx < NREP * NSEG; idx += NT) {
                ((int*)g_cntR[0])[idx] = 0;
                ((float*)g_s1R[0])[idx] = 0.f;
                ((float*)g_s2R[0])[idx] = 0.f;
            }
            for (int idx = t; idx < NSEG; idx += NT) g_cursor[0][idx] = 0;
        }
    }
    gridbar();

    for (int l = 0; l < NLAYER; l++) {
        const int par = l & 1, nxt = par ^ 1;
        const int uIdx = (l & 1) ^ 1;
        const int isLast = (l == NLAYER - 1);

        float* sa = X + XO_SA; float* sc = X + XO_SC; float* sthr = X + XO_STHR;
        float* sths = X + XO_STHS; int* sord = (int*)(X + XO_SORD); float* svr = X + XO_SVR;
        int* scnt = (int*)(X + XO_SCNT); float* ss1 = X + XO_SS1; float* ss2 = X + XO_SS2;
        float* WS = X + XO_WS; float* miscf = X + XO_MISC;

        // ================= P1: BN1 fold + lvl1 sort + lvl1 table build + hist =================
        if (t < H) {
            double mu = __ldcg(&g_sum[par][0]) * (1.0 / BATCH);
            double qq = __ldcg(&g_sum[par][1]) * (1.0 / BATCH);
            double var = qq - mu * mu;
            float meanu = (float)mu;
            float varu = (float)(var < 0.0 ? 0.0 : var);
            float v  = v1[l * H + t];
            float w1 = g1[l * H + t] * (v / fabsf(v));
            float r  = rsqrtf(w1 * w1 * varu + BN_EPS);
            float a  = w1 * bn1g[l * H + t] * r;
            float c  = bn1b[l * H + t] - a * meanu;
            sa[t] = a; sc[t] = c;
            sthr[t] = (a != 0.f) ? (-c / a) : CUDART_INF_F;
        }
        __syncthreads();
        if (t < H) {
            float th = sthr[t];
            int rank = 0;
            for (int j2 = 0; j2 < H; j2++) {
                float tj = sthr[j2];
                rank += (tj < th) || (tj == th && j2 < t);
            }
            sths[rank] = th; sord[rank] = t;
        }
        if (b == NB - 1) {  // zero next-parity buffers + next g_sum + next cursors
            for (int idx = t; idx < NREP * NSEG; idx += NT) {
                ((int*)g_cntR[nxt])[idx] = 0;
                ((float*)g_s1R[nxt])[idx] = 0.f;
                ((float*)g_s2R[nxt])[idx] = 0.f;
            }
            for (int idx = t; idx < NSEG; idx += NT) g_cursor[nxt][idx] = 0;
            if (t == 0) { g_sum[nxt][0] = 0.0; g_sum[nxt][1] = 0.0; }
        }
        __syncthreads();

        if (b < H) {  // build level-1 column j=b: register shfl reduce + scan
            const int j = b;
            if (t < H) svr[t] = v2[l * H * H + j * H + t];
            __syncthreads();
            float nv = (t < H) ? svr[t] * svr[t] : 0.f;
#pragma unroll
            for (int o = 16; o; o >>= 1) nv += __shfl_xor_sync(0xffffffffu, nv, o);
            if (lane == 0 && wid < 8) WS[wid] = nv;
            __syncthreads();
            if (t == 0) miscf[0] = g2[l * H + j] / sqrtf(WS[0] + WS[1] + WS[2] + WS[3]);
            __syncthreads();
            float wsc = miscf[0];

            float bA = 0.f, bB = 0.f;
            if (t < H) {
                float aa = sa[t], cc = sc[t], w = wsc * svr[t];
                if (aa < 0.f)                     { bA = w * aa; bB = w * cc; }
                else if (aa == 0.f && cc > 0.f)   { bB = w * cc; }
            }
            float dA = 0.f, dB = 0.f;
            if (t >= 1 && t <= H) {
                int kk = sord[t - 1];
                float aa = sa[kk], cc = sc[kk], w = wsc * svr[kk];
                float sgn = (aa > 0.f) ? 1.f : ((aa < 0.f) ? -1.f : 0.f);
                dA = sgn * w * aa; dB = sgn * w * cc;
            }
            float rA = bA, rB = bB;
#pragma unroll
            for (int o = 16; o; o >>= 1) {
                rA += __shfl_xor_sync(0xffffffffu, rA, o);
                rB += __shfl_xor_sync(0xffffffffu, rB, o);
            }
            if (lane == 0 && wid < 8) { WS[0 + wid] = rA; WS[8 + wid] = rB; }
            float sA = dA, sB = dB;
#pragma unroll
            for (int o = 1; o < 32; o <<= 1) {
                float uA = __shfl_up_sync(0xffffffffu, sA, o);
                float uB = __shfl_up_sync(0xffffffffu, sB, o);
                if (lane >= o) { sA += uA; sB += uB; }
            }
            if (lane == 31 && wid < 8) { WS[16 + wid] = sA; WS[24 + wid] = sB; }
            __syncthreads();
            if (t == 0) {
                miscf[1] = WS[0] + WS[1] + WS[2] + WS[3];
                miscf[2] = WS[8] + WS[9] + WS[10] + WS[11] + b2[l * H + j];
                float accA = 0.f, accB = 0.f;
#pragma unroll
                for (int w2 = 0; w2 < 5; w2++) {
                    WS[32 + w2] = accA; WS[40 + w2] = accB;
                    accA += WS[16 + w2]; accB += WS[24 + w2];
                }
            }
            __syncthreads();
            if (t <= H) {
                float2 val = make_float2(miscf[1] + WS[32 + wid] + sA,
                                         miscf[2] + WS[40 + wid] + sB);
                __stcg(((float2*)g_tab) + t * H + j, val);
            }
        }
        __syncthreads();

        // hist: register-accumulated hot tails (0 and H), smem atomics for interior
        for (int i = t; i < NSEG; i += NT) { scnt[i] = 0; ss1[i] = 0.f; ss2[i] = 0.f; }
        __syncthreads();
        {
            float as1l = 0.f, as2l = 0.f, as1h = 0.f, as2h = 0.f;
            int acl = 0, ach = 0;
            for (int i = b * NT + t; i < BATCH; i += NB * NT) {
                float4 p = __ldcg(&g_xs[i]);
                float u = uIdx ? p.y : p.x;
                int m = 0;
#pragma unroll
                for (int s = 64; s >= 1; s >>= 1) { int nm = m + s; if (sths[nm - 1] < u) m = nm; }
                if (sths[H - 1] < u) m = H;   // 7-step count saturates at 127
                __stcg(&g_mseg[i], (unsigned char)m);
                float u2 = u * u;
                if (m == 0)      { as1l += u; as2l += u2; acl++; }
                else if (m == H) { as1h += u; as2h += u2; ach++; }
                else {
                    atomicAdd(&scnt[m], 1);
                    atomicAdd(&ss1[m], u);
                    atomicAdd(&ss2[m], u2);
                }
            }
#pragma unroll
            for (int o = 16; o; o >>= 1) {
                as1l += __shfl_xor_sync(0xffffffffu, as1l, o);
                as2l += __shfl_xor_sync(0xffffffffu, as2l, o);
                as1h += __shfl_xor_sync(0xffffffffu, as1h, o);
                as2h += __shfl_xor_sync(0xffffffffu, as2h, o);
                acl  += __shfl_xor_sync(0xffffffffu, acl, o);
                ach  += __shfl_xor_sync(0xffffffffu, ach, o);
            }
            if (lane == 0) {
                if (acl) { atomicAdd(&scnt[0], acl); atomicAdd(&ss1[0], as1l); atomicAdd(&ss2[0], as2l); }
                if (ach) { atomicAdd(&scnt[H], ach); atomicAdd(&ss1[H], as1h); atomicAdd(&ss2[H], as2h); }
            }
        }
        __syncthreads();
        {
            int r = b & (NREP - 1);
            for (int i = t; i < NSEG; i += NT) {
                if (scnt[i]) {
                    atomicAdd(&g_cntR[par][r][i], scnt[i]);
                    atomicAdd(&g_s1R[par][r][i], ss1[i]);
                    atomicAdd(&g_s2R[par][r][i], ss2[i]);
                }
            }
        }
        gridbar();

        // ====== P3: offsets + scatter + ghbh + table fold (hidden behind scatter) ======
        {
            int* ecnt = (int*)(X + XO_SCNT);
            int* eoff = (int*)(X + XO_EOFF);
            int* bcnt = (int*)(X + XO_SS1);
            int* bbase = (int*)(X + XO_SS2);
            if (t < NSEG) {
                int c = 0;
#pragma unroll
                for (int r = 0; r < NREP; r++) c += __ldcg(&g_cntR[par][r][t]);
                ecnt[t] = c;
            }
            for (int i = t; i < NSEG; i += NT) bcnt[i] = 0;
            __syncthreads();
            if (t == 0) {
                int run = 0;
                for (int s = 0; s < NSEG; s++) { eoff[s] = run; run += (ecnt[s] + 31) & ~31; }
                eoff[NSEG] = run;
                if (b == 0) g_ptotal = run;
            }
            __syncthreads();
            int m0s = 0, m1s = 0, r0s = 0, r1s = 0, i0 = 0, i1 = 0;
            if (b < H) {
                i0 = b * 2048 + t; i1 = i0 + 1024;
                m0s = __ldcg(&g_mseg[i0]);
                m1s = __ldcg(&g_mseg[i1]);
                r0s = atomicAdd(&bcnt[m0s], 1);
                r1s = atomicAdd(&bcnt[m1s], 1);
            }
            __syncthreads();
            if (b < H && t < NSEG)
                bbase[t] = bcnt[t] ? atomicAdd(&g_cursor[par][t], bcnt[t]) : 0;
            __syncthreads();
            if (b < H) {
                __stcg(&g_perm[eoff[m0s] + bbase[m0s] + r0s], ((unsigned)m0s << 18) | (unsigned)i0);
                __stcg(&g_perm[eoff[m1s] + bbase[m1s] + r1s], ((unsigned)m1s << 18) | (unsigned)i1);
            }
            if (b < NSEG) {
                for (int p = eoff[b] + ecnt[b] + t; p < eoff[b + 1]; p += NT)
                    __stcg(&g_perm[p], INVALID);
            }
            // ghbh[j=b] (shfl reduce) THEN fold column j=b into g_tabF
            if (b < H) {
                const int j = b;
                float t1 = 0.f, t2 = 0.f;
                if (t < NSEG) {
                    float S1 = 0.f, S2 = 0.f;
#pragma unroll
                    for (int r = 0; r < NREP; r++) {
                        S1 += __ldcg(&g_s1R[par][r][t]);
                        S2 += __ldcg(&g_s2R[par][r][t]);
                    }
                    float N = (float)ecnt[t];
                    float2 ab = __ldcg(((const float2*)g_tab) + t * H + j);
                    t1 = ab.x * S1 + ab.y * N;
                    t2 = ab.x * (ab.x * S2 + 2.f * ab.y * S1) + ab.y * ab.y * N;
                }
#pragma unroll
                for (int o = 16; o; o >>= 1) {
                    t1 += __shfl_xor_sync(0xffffffffu, t1, o);
                    t2 += __shfl_xor_sync(0xffffffffu, t2, o);
                }
                if (lane == 0 && wid < 8) { WS[0 + wid] = t1; WS[8 + wid] = t2; }
                __syncthreads();
                if (t == 0) {
                    float m1 = WS[0] + WS[1] + WS[2] + WS[3] + WS[4];
                    float m2 = WS[8] + WS[9] + WS[10] + WS[11] + WS[12];
                    float mean = m1 * (1.f / BATCH);
                    float var  = m2 * (1.f / BATCH) - mean * mean;
                    if (var < 0.f) var = 0.f;
                    float gh = bn2g[l * H + j] * rsqrtf(var + BN_EPS);
                    float bh = bn2b[l * H + j] - gh * mean;
                    miscf[4] = gh; miscf[5] = bh;
                }
                __syncthreads();
                float gh = miscf[4], bh = miscf[5];
                if (t < NSEG) {
                    float2 ab = __ldcg(((const float2*)g_tab) + t * H + j);
                    float2 fv = make_float2(gh * ab.x, fmaf(gh, ab.y, bh));
                    __stcg(((float2*)g_tabF) + t * H + j, fv);
                }
            }
        }
        gridbar();

        // ================= P4: TMA bulk copy folded table -> smem, then apply =========
        {
            if (t == 0) {
                asm volatile("mbarrier.init.shared.b64 [%0], 1;" :: "r"(mbar_sa) : "memory");
            }
            __syncthreads();
            if (t == 0) {
                asm volatile("mbarrier.arrive.expect_tx.shared.b64 _, [%0], %1;"
                             :: "r"(mbar_sa), "r"((unsigned)TAB_BYTES) : "memory");
                asm volatile("cp.async.bulk.shared::cta.global.mbarrier::complete_tx::bytes "
                             "[%0], [%1], %2, [%3];"
                             :: "r"(stab_sa), "l"(tabF_ga), "r"((unsigned)TAB_BYTES), "r"(mbar_sa)
                             : "memory");
            }
            // overlap: fill wf4 while the bulk copy is in flight
            for (int jj = t; jj < 64; jj += NT) {
                int j0 = 2 * jj, j1 = 2 * jj + 1;
                wf4[jj] = make_float4(wf[(l * 2 + 0) * H + j0], wf[(l * 2 + 1) * H + j0],
                                      wf[(l * 2 + 0) * H + j1], wf[(l * 2 + 1) * H + j1]);
            }
            asm volatile(
                "{\n\t.reg .pred p;\n"
                "WAITLP%=:\n\t"
                "mbarrier.try_wait.parity.acquire.cta.shared::cta.b64 p, [%0], 0, 0x989680;\n\t"
                "@!p bra WAITLP%=;\n\t}"
                :: "r"(mbar_sa) : "memory");
            __syncthreads();

            const int P = __ldcg(&g_ptotal);
            float bf0 = bf[l * 2], bf1 = bf[l * 2 + 1];
            float kS = 0.f, cS = 0.f, kQ = 0.f, cQ = 0.f;
            int gw = b * 32 + wid, nw = NB * 32;

            for (int base = gw * 32; base < P; base += nw * 32) {
                unsigned pv  = __ldcg(&g_perm[base + lane]);
                unsigned pv0 = __shfl_sync(0xffffffffu, pv, 0);   // lane 0 valid (32-aligned)
                int m0 = (int)(pv0 >> 18);
                bool valid = (pv != INVALID);
                unsigned i = valid ? (pv & 0x3FFFFu) : 0u;

                float4 rec = __ldcg(&g_xs[i]);   // (x0, x1, sldj, -) one scattered 16B load
                float u  = uIdx ? rec.y : rec.x;
                float xo = uIdx ? rec.x : rec.y;

                const float4* row = stab4 + m0 * 64;
                float st0a = 0.f, st1a = 0.f, st0b = 0.f, st1b = 0.f;
#pragma unroll 8
                for (int c = 0; c < 64; c += 2) {
                    float4 tv = row[c];     float4 w4 = wf4[c];
                    float h0 = fmaxf(fmaf(tv.x, u, tv.y), 0.f);
                    float h1 = fmaxf(fmaf(tv.z, u, tv.w), 0.f);
                    st0a = fmaf(w4.x, h0, fmaf(w4.z, h1, st0a));
                    st1a = fmaf(w4.y, h0, fmaf(w4.w, h1, st1a));
                    float4 tv2 = row[c + 1]; float4 w42 = wf4[c + 1];
                    float h2 = fmaxf(fmaf(tv2.x, u, tv2.y), 0.f);
                    float h3 = fmaxf(fmaf(tv2.z, u, tv2.w), 0.f);
                    st0b = fmaf(w42.x, h2, fmaf(w42.z, h3, st0b));
                    st1b = fmaf(w42.y, h2, fmaf(w42.w, h3, st1b));
                }
                float st0 = st0a + st0b + bf0;
                float st1 = st1a + st1b + bf1;
                float e2  = __expf(2.f * st0);
                float sv  = 1.f - 2.f * __fdividef(1.f, e2 + 1.f);   // tanh
                float y   = fmaf(__expf(sv), xo, st1);

                if (valid) {
                    float sld = rec.z + sv;
                    if (!isLast) {
                        // write back packed record: component uIdx stays u, other becomes y
                        float nx0 = uIdx ? y : u;
                        float nx1 = uIdx ? u : y;
                        __stcg(&g_xs[i], make_float4(nx0, nx1, sld, 0.f));
                        { float yk = y - cS;  float tk = kS + yk; cS = (tk - kS) - yk; kS = tk; }
                        float yy = y * y;
                        { float yk = yy - cQ; float tk = kQ + yk; cQ = (tk - kQ) - yk; kQ = tk; }
                    } else {
                        float zu = __fdividef(1.f, 1.f + __expf(-u));
                        float zo = __fdividef(1.f, 1.f + __expf(-y));
                        sld += __logf(zu * (1.f - zu) + FLOW_EPS) + __logf(zo * (1.f - zo) + FLOW_EPS);
                        out[2 * i + uIdx] = zu;
                        out[2 * i + (1 - uIdx)] = zo;
                        out[2 * BATCH + i] = sld;
                    }
                }
            }

            if (!isLast) {
                double s = (double)kS, q = (double)kQ;
                for (int off = 16; off; off >>= 1) {
                    s += __shfl_down_sync(0xffffffffu, s, off);
                    q += __shfl_down_sync(0xffffffffu, q, off);
                }
                __shared__ double rs[32], rq[32];
                if (!lane) { rs[wid] = s; rq[wid] = q; }
                __syncthreads();
                if (!wid) {
                    s = (lane < NT / 32) ? rs[lane] : 0.0;
                    q = (lane < NT / 32) ? rq[lane] : 0.0;
                    for (int off = 16; off; off >>= 1) {
                        s += __shfl_down_sync(0xffffffffu, s, off);
                        q += __shfl_down_sync(0xffffffffu, q, off);
                    }
                    if (!lane) { atomicAdd(&g_sum[nxt][0], s); atomicAdd(&g_sum[nxt][1], q); }
                }
            }
        }
        if (!isLast) gridbar();
    }
}

// ---------------- host launcher ----------------
extern "C" void kernel_launch(void* const* d_in, const int* in_sizes, int n_in,
                              void* d_out, int out_size)
{
    const float* x    = (const float*)d_in[0];
    const float* v1   = (const float*)d_in[1];
    const float* g1   = (const float*)d_in[2];
    const float* b1   = (const float*)d_in[3];
    const float* bn1g = (const float*)d_in[4];
    const float* bn1b = (const float*)d_in[5];
    const float* v2   = (const float*)d_in[6];
    const float* g2   = (const float*)d_in[7];
    const float* b2   = (const float*)d_in[8];
    const float* bn2g = (const float*)d_in[9];
    const float* bn2b = (const float*)d_in[10];
    const float* wf   = (const float*)d_in[11];
    const float* bf   = (const float*)d_in[12];
    float* out = (float*)d_out;

    cudaFuncSetAttribute(k_all, cudaFuncAttributeMaxDynamicSharedMemorySize, SMEM_ALL);
    k_all<<<NB, NT, SMEM_ALL>>>(x, v1, g1, b1, bn1g, bn1b, v2, g2, b2,
                                bn2g, bn2b, wf, bf, out);
    (void)in_sizes; (void)n_in; (void)out_size;
}

// round 17
// speedup vs baseline: 1.2985x; 1.0907x over previous
#include <cuda_runtime.h>
#include <math_constants.h>

#define BATCH 262144
#define NLAYER 8
#define H 128
#define NSEG 129
#define BN_EPS 1e-5f
#define FLOW_EPS 1e-4f
#define INVALID 0xFFFFFFFFu
#define NREP 4
#define NB 148
#define NT 1024
#define TAB_BYTES (NSEG * 64 * 16)   // 132096

// ---------------- device scratch (no allocs allowed) ----------------
__device__ unsigned g_arrive = 0, g_release = 0;   // grid barrier (monotonic, replay-safe)
__device__ double g_sum[2][2];                     // [parity][s,q]
__device__ int    g_cntR[2][NREP][NSEG];
__device__ float  g_s1R[2][NREP][NSEG], g_s2R[2][NREP][NSEG];
__device__ __align__(16) float g_tab[NSEG * H * 2];   // raw level-1 table (A,B per m,j)
__device__ __align__(16) float g_tabF[NSEG * H * 2];  // BN2-folded table (a,b per m,j)
__device__ int    g_cursor[2][NSEG];
__device__ int    g_ptotal;
__device__ unsigned g_perm[BATCH + NSEG * 64];        // 64-aligned segment regions
__device__ unsigned char g_mseg[BATCH];
__device__ __align__(16) float4 g_xs[BATCH];          // (x0, x1, sldj, pad) per sample

// grid-wide barrier: all NB blocks resident by construction
__device__ __forceinline__ void gridbar()
{
    __syncthreads();
    if (threadIdx.x == 0) {
        unsigned old = *(volatile unsigned*)&g_release;
        __threadfence();
        if (atomicAdd(&g_arrive, 1) == NB - 1) {
            atomicExch(&g_arrive, 0);
            __threadfence();
            atomicExch(&g_release, old + 1);
        } else {
            while (*(volatile unsigned*)&g_release == old) __nanosleep(32);
        }
        __threadfence();
    }
    __syncthreads();
}

// shared layout (float offsets) in the X region after the float4 table area
#define XO_SA    0
#define XO_SC    128
#define XO_STHR  256
#define XO_STHS  384
#define XO_SORD  512
#define XO_SVR   640
#define XO_SCNT  768        // int[129]
#define XO_SS1   900        // hist floats / P3 bcnt ints
#define XO_SS2   1032       // hist floats / P3 bbase ints
#define XO_EOFF  1164       // int[130]
#define XO_WS    1552       // warp partials (48)
#define XO_MISC  1600       // 8
#define XO_MBAR  1608       // mbarrier (2 floats, 8B aligned)
#define X_FLOATS 1616
#define SMEM_ALL ((NSEG * 64 + 64) * 16 + X_FLOATS * 4)

__global__ void __launch_bounds__(NT, 1) k_all(
    const float* __restrict__ x,
    const float* __restrict__ v1,  const float* __restrict__ g1,  const float* __restrict__ b1,
    const float* __restrict__ bn1g,const float* __restrict__ bn1b,
    const float* __restrict__ v2,  const float* __restrict__ g2,  const float* __restrict__ b2,
    const float* __restrict__ bn2g,const float* __restrict__ bn2b,
    const float* __restrict__ wf,  const float* __restrict__ bf,
    float* __restrict__ out)
{
    extern __shared__ float sm[];
    float4* stab4 = (float4*)sm;                 // NSEG*64 float4 folded table
    float4* wf4   = stab4 + NSEG * 64;           // 64 float4
    float*  X     = (float*)(wf4 + 64);

    const int t = threadIdx.x, b = blockIdx.x;
    const int lane = t & 31, wid = t >> 5;

    // shared-space addresses for mbarrier + table (for cp.async.bulk)
    unsigned mbar_sa, stab_sa;
    asm("{ .reg .u64 ta; cvta.to.shared.u64 ta, %1; cvt.u32.u64 %0, ta; }"
        : "=r"(mbar_sa) : "l"((void*)(X + XO_MBAR)));
    asm("{ .reg .u64 ta; cvta.to.shared.u64 ta, %1; cvt.u32.u64 %0, ta; }"
        : "=r"(stab_sa) : "l"((void*)stab4));
    unsigned long long tabF_ga;
    asm("cvta.to.global.u64 %0, %1;" : "=l"(tabF_ga) : "l"((void*)g_tabF));

    // ================= P0: build packed records; stats of x[:,1] =================
    {
        float kS = 0.f, cS = 0.f, kQ = 0.f, cQ = 0.f;
        for (int i = b * NT + t; i < BATCH; i += NB * NT) {
            float2 p = ((const float2*)x)[i];
            __stcg(&g_xs[i], make_float4(p.x, p.y, 0.f, 0.f));
            float v = p.y;
            { float yk = v - cS; float tk = kS + yk; cS = (tk - kS) - yk; kS = tk; }
            float v2s = v * v;
            { float yk = v2s - cQ; float tk = kQ + yk; cQ = (tk - kQ) - yk; kQ = tk; }
        }
        double s = (double)kS, q = (double)kQ;
        for (int off = 16; off; off >>= 1) {
            s += __shfl_down_sync(0xffffffffu, s, off);
            q += __shfl_down_sync(0xffffffffu, q, off);
        }
        __shared__ double ss[32], sq[32];
        if (!lane) { ss[wid] = s; sq[wid] = q; }
        __syncthreads();
        if (!wid) {
            s = (lane < NT / 32) ? ss[lane] : 0.0;
            q = (lane < NT / 32) ? sq[lane] : 0.0;
            for (int off = 16; off; off >>= 1) {
                s += __shfl_down_sync(0xffffffffu, s, off);
                q += __shfl_down_sync(0xffffffffu, q, off);
            }
            if (!lane) { atomicAdd(&g_sum[0][0], s); atomicAdd(&g_sum[0][1], q); }
        }
        if (b == 1) {   // parity-0 buffers zero at start of each replay (idempotent)
            for (int idx = t; idx < NREP * NSEG; idx += NT) {
                ((int*)g_cntR[0])[idx] = 0;
                ((float*)g_s1R[0])[idx] = 0.f;
                ((float*)g_s2R[0])[idx] = 0.f;
            }
            for (int idx = t; idx < NSEG; idx += NT) g_cursor[0][idx] = 0;
        }
    }
    gridbar();

    for (int l = 0; l < NLAYER; l++) {
        const int par = l & 1, nxt = par ^ 1;
        const int uIdx = (l & 1) ^ 1;
        const int isLast = (l == NLAYER - 1);

        float* sa = X + XO_SA; float* sc = X + XO_SC; float* sthr = X + XO_STHR;
        float* sths = X + XO_STHS; int* sord = (int*)(X + XO_SORD); float* svr = X + XO_SVR;
        int* scnt = (int*)(X + XO_SCNT); float* ss1 = X + XO_SS1; float* ss2 = X + XO_SS2;
        float* WS = X + XO_WS; float* miscf = X + XO_MISC;

        // ================= P1: BN1 fold + lvl1 sort + lvl1 table build + hist =================
        if (t < H) {
            double mu = __ldcg(&g_sum[par][0]) * (1.0 / BATCH);
            double qq = __ldcg(&g_sum[par][1]) * (1.0 / BATCH);
            double var = qq - mu * mu;
            float meanu = (float)mu;
            float varu = (float)(var < 0.0 ? 0.0 : var);
            float v  = v1[l * H + t];
            float w1 = g1[l * H + t] * (v / fabsf(v));
            float r  = rsqrtf(w1 * w1 * varu + BN_EPS);
            float a  = w1 * bn1g[l * H + t] * r;
            float c  = bn1b[l * H + t] - a * meanu;
            sa[t] = a; sc[t] = c;
            sthr[t] = (a != 0.f) ? (-c / a) : CUDART_INF_F;
        }
        __syncthreads();
        if (t < H) {
            float th = sthr[t];
            int rank = 0;
            for (int j2 = 0; j2 < H; j2++) {
                float tj = sthr[j2];
                rank += (tj < th) || (tj == th && j2 < t);
            }
            sths[rank] = th; sord[rank] = t;
        }
        if (b == NB - 1) {  // zero next-parity buffers + next g_sum + next cursors
            for (int idx = t; idx < NREP * NSEG; idx += NT) {
                ((int*)g_cntR[nxt])[idx] = 0;
                ((float*)g_s1R[nxt])[idx] = 0.f;
                ((float*)g_s2R[nxt])[idx] = 0.f;
            }
            for (int idx = t; idx < NSEG; idx += NT) g_cursor[nxt][idx] = 0;
            if (t == 0) { g_sum[nxt][0] = 0.0; g_sum[nxt][1] = 0.0; }
        }
        __syncthreads();

        if (b < H) {  // build level-1 column j=b: register shfl reduce + scan
            const int j = b;
            if (t < H) svr[t] = v2[l * H * H + j * H + t];
            __syncthreads();
            float nv = (t < H) ? svr[t] * svr[t] : 0.f;
#pragma unroll
            for (int o = 16; o; o >>= 1) nv += __shfl_xor_sync(0xffffffffu, nv, o);
            if (lane == 0 && wid < 8) WS[wid] = nv;
            __syncthreads();
            if (t == 0) miscf[0] = g2[l * H + j] / sqrtf(WS[0] + WS[1] + WS[2] + WS[3]);
            __syncthreads();
            float wsc = miscf[0];

            float bA = 0.f, bB = 0.f;
            if (t < H) {
                float aa = sa[t], cc = sc[t], w = wsc * svr[t];
                if (aa < 0.f)                     { bA = w * aa; bB = w * cc; }
                else if (aa == 0.f && cc > 0.f)   { bB = w * cc; }
            }
            float dA = 0.f, dB = 0.f;
            if (t >= 1 && t <= H) {
                int kk = sord[t - 1];
                float aa = sa[kk], cc = sc[kk], w = wsc * svr[kk];
                float sgn = (aa > 0.f) ? 1.f : ((aa < 0.f) ? -1.f : 0.f);
                dA = sgn * w * aa; dB = sgn * w * cc;
            }
            float rA = bA, rB = bB;
#pragma unroll
            for (int o = 16; o; o >>= 1) {
                rA += __shfl_xor_sync(0xffffffffu, rA, o);
                rB += __shfl_xor_sync(0xffffffffu, rB, o);
            }
            if (lane == 0 && wid < 8) { WS[0 + wid] = rA; WS[8 + wid] = rB; }
            float sA = dA, sB = dB;
#pragma unroll
            for (int o = 1; o < 32; o <<= 1) {
                float uA = __shfl_up_sync(0xffffffffu, sA, o);
                float uB = __shfl_up_sync(0xffffffffu, sB, o);
                if (lane >= o) { sA += uA; sB += uB; }
            }
            if (lane == 31 && wid < 8) { WS[16 + wid] = sA; WS[24 + wid] = sB; }
            __syncthreads();
            if (t == 0) {
                miscf[1] = WS[0] + WS[1] + WS[2] + WS[3];
                miscf[2] = WS[8] + WS[9] + WS[10] + WS[11] + b2[l * H + j];
                float accA = 0.f, accB = 0.f;
#pragma unroll
                for (int w2 = 0; w2 < 5; w2++) {
                    WS[32 + w2] = accA; WS[40 + w2] = accB;
                    accA += WS[16 + w2]; accB += WS[24 + w2];
                }
            }
            __syncthreads();
            if (t <= H) {
                float2 val = make_float2(miscf[1] + WS[32 + wid] + sA,
                                         miscf[2] + WS[40 + wid] + sB);
                __stcg(((float2*)g_tab) + t * H + j, val);
            }
        }
        __syncthreads();

        // hist: register-accumulated hot tails (0 and H), smem atomics for interior
        for (int i = t; i < NSEG; i += NT) { scnt[i] = 0; ss1[i] = 0.f; ss2[i] = 0.f; }
        __syncthreads();
        {
            float as1l = 0.f, as2l = 0.f, as1h = 0.f, as2h = 0.f;
            int acl = 0, ach = 0;
            for (int i = b * NT + t; i < BATCH; i += NB * NT) {
                float4 p = __ldcg(&g_xs[i]);
                float u = uIdx ? p.y : p.x;
                int m = 0;
#pragma unroll
                for (int s = 64; s >= 1; s >>= 1) { int nm = m + s; if (sths[nm - 1] < u) m = nm; }
                if (sths[H - 1] < u) m = H;   // 7-step count saturates at 127
                __stcg(&g_mseg[i], (unsigned char)m);
                float u2 = u * u;
                if (m == 0)      { as1l += u; as2l += u2; acl++; }
                else if (m == H) { as1h += u; as2h += u2; ach++; }
                else {
                    atomicAdd(&scnt[m], 1);
                    atomicAdd(&ss1[m], u);
                    atomicAdd(&ss2[m], u2);
                }
            }
#pragma unroll
            for (int o = 16; o; o >>= 1) {
                as1l += __shfl_xor_sync(0xffffffffu, as1l, o);
                as2l += __shfl_xor_sync(0xffffffffu, as2l, o);
                as1h += __shfl_xor_sync(0xffffffffu, as1h, o);
                as2h += __shfl_xor_sync(0xffffffffu, as2h, o);
                acl  += __shfl_xor_sync(0xffffffffu, acl, o);
                ach  += __shfl_xor_sync(0xffffffffu, ach, o);
            }
            if (lane == 0) {
                if (acl) { atomicAdd(&scnt[0], acl); atomicAdd(&ss1[0], as1l); atomicAdd(&ss2[0], as2l); }
                if (ach) { atomicAdd(&scnt[H], ach); atomicAdd(&ss1[H], as1h); atomicAdd(&ss2[H], as2h); }
            }
        }
        __syncthreads();
        {
            int r = b & (NREP - 1);
            for (int i = t; i < NSEG; i += NT) {
                if (scnt[i]) {
                    atomicAdd(&g_cntR[par][r][i], scnt[i]);
                    atomicAdd(&g_s1R[par][r][i], ss1[i]);
                    atomicAdd(&g_s2R[par][r][i], ss2[i]);
                }
            }
        }
        gridbar();

        // ====== P3: offsets (64-aligned) + scatter + ghbh + table fold ======
        {
            int* ecnt = (int*)(X + XO_SCNT);
            int* eoff = (int*)(X + XO_EOFF);
            int* bcnt = (int*)(X + XO_SS1);
            int* bbase = (int*)(X + XO_SS2);
            if (t < NSEG) {
                int c = 0;
#pragma unroll
                for (int r = 0; r < NREP; r++) c += __ldcg(&g_cntR[par][r][t]);
                ecnt[t] = c;
            }
            for (int i = t; i < NSEG; i += NT) bcnt[i] = 0;
            __syncthreads();
            if (t == 0) {
                int run = 0;
                for (int s = 0; s < NSEG; s++) { eoff[s] = run; run += (ecnt[s] + 63) & ~63; }
                eoff[NSEG] = run;
                if (b == 0) g_ptotal = run;
            }
            __syncthreads();
            int m0s = 0, m1s = 0, r0s = 0, r1s = 0, i0 = 0, i1 = 0;
            if (b < H) {
                i0 = b * 2048 + t; i1 = i0 + 1024;
                m0s = __ldcg(&g_mseg[i0]);
                m1s = __ldcg(&g_mseg[i1]);
                r0s = atomicAdd(&bcnt[m0s], 1);
                r1s = atomicAdd(&bcnt[m1s], 1);
            }
            __syncthreads();
            if (b < H && t < NSEG)
                bbase[t] = bcnt[t] ? atomicAdd(&g_cursor[par][t], bcnt[t]) : 0;
            __syncthreads();
            if (b < H) {
                __stcg(&g_perm[eoff[m0s] + bbase[m0s] + r0s], ((unsigned)m0s << 18) | (unsigned)i0);
                __stcg(&g_perm[eoff[m1s] + bbase[m1s] + r1s], ((unsigned)m1s << 18) | (unsigned)i1);
            }
            if (b < NSEG) {
                for (int p = eoff[b] + ecnt[b] + t; p < eoff[b + 1]; p += NT)
                    __stcg(&g_perm[p], INVALID);
            }
            // ghbh[j=b] (shfl reduce) THEN fold column j=b into g_tabF
            if (b < H) {
                const int j = b;
                float t1 = 0.f, t2 = 0.f;
                if (t < NSEG) {
                    float S1 = 0.f, S2 = 0.f;
#pragma unroll
                    for (int r = 0; r < NREP; r++) {
                        S1 += __ldcg(&g_s1R[par][r][t]);
                        S2 += __ldcg(&g_s2R[par][r][t]);
                    }
                    float N = (float)ecnt[t];
                    float2 ab = __ldcg(((const float2*)g_tab) + t * H + j);
                    t1 = ab.x * S1 + ab.y * N;
                    t2 = ab.x * (ab.x * S2 + 2.f * ab.y * S1) + ab.y * ab.y * N;
                }
#pragma unroll
                for (int o = 16; o; o >>= 1) {
                    t1 += __shfl_xor_sync(0xffffffffu, t1, o);
                    t2 += __shfl_xor_sync(0xffffffffu, t2, o);
                }
                if (lane == 0 && wid < 8) { WS[0 + wid] = t1; WS[8 + wid] = t2; }
                __syncthreads();
                if (t == 0) {
                    float m1 = WS[0] + WS[1] + WS[2] + WS[3] + WS[4];
                    float m2 = WS[8] + WS[9] + WS[10] + WS[11] + WS[12];
                    float mean = m1 * (1.f / BATCH);
                    float var  = m2 * (1.f / BATCH) - mean * mean;
                    if (var < 0.f) var = 0.f;
                    float gh = bn2g[l * H + j] * rsqrtf(var + BN_EPS);
                    float bh = bn2b[l * H + j] - gh * mean;
                    miscf[4] = gh; miscf[5] = bh;
                }
                __syncthreads();
                float gh = miscf[4], bh = miscf[5];
                if (t < NSEG) {
                    float2 ab = __ldcg(((const float2*)g_tab) + t * H + j);
                    float2 fv = make_float2(gh * ab.x, fmaf(gh, ab.y, bh));
                    __stcg(((float2*)g_tabF) + t * H + j, fv);
                }
            }
        }
        gridbar();

        // ================= P4: TMA bulk copy folded table -> smem, then apply (64/warp) =========
        {
            if (t == 0) {
                asm volatile("mbarrier.init.shared.b64 [%0], 1;" :: "r"(mbar_sa) : "memory");
            }
            __syncthreads();
            if (t == 0) {
                asm volatile("mbarrier.arrive.expect_tx.shared.b64 _, [%0], %1;"
                             :: "r"(mbar_sa), "r"((unsigned)TAB_BYTES) : "memory");
                asm volatile("cp.async.bulk.shared::cta.global.mbarrier::complete_tx::bytes "
                             "[%0], [%1], %2, [%3];"
                             :: "r"(stab_sa), "l"(tabF_ga), "r"((unsigned)TAB_BYTES), "r"(mbar_sa)
                             : "memory");
            }
            for (int jj = t; jj < 64; jj += NT) {
                int j0 = 2 * jj, j1 = 2 * jj + 1;
                wf4[jj] = make_float4(wf[(l * 2 + 0) * H + j0], wf[(l * 2 + 1) * H + j0],
                                      wf[(l * 2 + 0) * H + j1], wf[(l * 2 + 1) * H + j1]);
            }
            asm volatile(
                "{\n\t.reg .pred p;\n"
                "WAITLP%=:\n\t"
                "mbarrier.try_wait.parity.acquire.cta.shared::cta.b64 p, [%0], 0, 0x989680;\n\t"
                "@!p bra WAITLP%=;\n\t}"
                :: "r"(mbar_sa) : "memory");
            __syncthreads();

            const int P = __ldcg(&g_ptotal);
            float bf0 = bf[l * 2], bf1 = bf[l * 2 + 1];
            float accS = 0.f, accQ = 0.f;
            int gw = b * 32 + wid, nw = NB * 32;

            for (int base = gw * 64; base < P; base += nw * 64) {
                unsigned pva = __ldcg(&g_perm[base + lane]);
                unsigned pvb = __ldcg(&g_perm[base + 32 + lane]);
                unsigned pv0 = __shfl_sync(0xffffffffu, pva, 0);   // region start: always valid
                int m0 = (int)(pv0 >> 18);
                bool va = (pva != INVALID), vb = (pvb != INVALID);
                unsigned ia = va ? (pva & 0x3FFFFu) : 0u;
                unsigned ib = vb ? (pvb & 0x3FFFFu) : 0u;

                float4 ra = __ldcg(&g_xs[ia]);
                float4 rb = __ldcg(&g_xs[ib]);
                float u0 = uIdx ? ra.y : ra.x, xo0 = uIdx ? ra.x : ra.y;
                float u1 = uIdx ? rb.y : rb.x, xo1 = uIdx ? rb.x : rb.y;

                const float4* row = stab4 + m0 * 64;
                float A0 = 0.f, B0 = 0.f, A1 = 0.f, B1 = 0.f;
#pragma unroll 8
                for (int c = 0; c < 64; c++) {
                    float4 tv = row[c]; float4 w4 = wf4[c];
                    float h00 = fmaxf(fmaf(tv.x, u0, tv.y), 0.f);
                    float h10 = fmaxf(fmaf(tv.z, u0, tv.w), 0.f);
                    float h01 = fmaxf(fmaf(tv.x, u1, tv.y), 0.f);
                    float h11 = fmaxf(fmaf(tv.z, u1, tv.w), 0.f);
                    A0 = fmaf(w4.x, h00, fmaf(w4.z, h10, A0));
                    B0 = fmaf(w4.y, h00, fmaf(w4.w, h10, B0));
                    A1 = fmaf(w4.x, h01, fmaf(w4.z, h11, A1));
                    B1 = fmaf(w4.y, h01, fmaf(w4.w, h11, B1));
                }
                // sample a
                {
                    float st0 = A0 + bf0, st1 = B0 + bf1;
                    float e2  = __expf(2.f * st0);
                    float sv  = 1.f - 2.f * __fdividef(1.f, e2 + 1.f);
                    float y   = fmaf(__expf(sv), xo0, st1);
                    if (va) {
                        float sld = ra.z + sv;
                        if (!isLast) {
                            float nx0 = uIdx ? y : u0;
                            float nx1 = uIdx ? u0 : y;
                            __stcg(&g_xs[ia], make_float4(nx0, nx1, sld, 0.f));
                            accS += y; accQ += y * y;
                        } else {
                            float zu = __fdividef(1.f, 1.f + __expf(-u0));
                            float zo = __fdividef(1.f, 1.f + __expf(-y));
                            sld += __logf(zu * (1.f - zu) + FLOW_EPS) + __logf(zo * (1.f - zo) + FLOW_EPS);
                            out[2 * ia + uIdx] = zu;
                            out[2 * ia + (1 - uIdx)] = zo;
                            out[2 * BATCH + ia] = sld;
                        }
                    }
                }
                // sample b
                {
                    float st0 = A1 + bf0, st1 = B1 + bf1;
                    float e2  = __expf(2.f * st0);
                    float sv  = 1.f - 2.f * __fdividef(1.f, e2 + 1.f);
                    float y   = fmaf(__expf(sv), xo1, st1);
                    if (vb) {
                        float sld = rb.z + sv;
                        if (!isLast) {
                            float nx0 = uIdx ? y : u1;
                            float nx1 = uIdx ? u1 : y;
                            __stcg(&g_xs[ib], make_float4(nx0, nx1, sld, 0.f));
                            accS += y; accQ += y * y;
                        } else {
                            float zu = __fdividef(1.f, 1.f + __expf(-u1));
                            float zo = __fdividef(1.f, 1.f + __expf(-y));
                            sld += __logf(zu * (1.f - zu) + FLOW_EPS) + __logf(zo * (1.f - zo) + FLOW_EPS);
                            out[2 * ib + uIdx] = zu;
                            out[2 * ib + (1 - uIdx)] = zo;
                            out[2 * BATCH + ib] = sld;
                        }
                    }
                }
            }

            if (!isLast) {
                double s = (double)accS, q = (double)accQ;
                for (int off = 16; off; off >>= 1) {
                    s += __shfl_down_sync(0xffffffffu, s, off);
                    q += __shfl_down_sync(0xffffffffu, q, off);
                }
                __shared__ double rs[32], rq[32];
                if (!lane) { rs[wid] = s; rq[wid] = q; }
                __syncthreads();
                if (!wid) {
                    s = (lane < NT / 32) ? rs[lane] : 0.0;
                    q = (lane < NT / 32) ? rq[lane] : 0.0;
                    for (int off = 16; off; off >>= 1) {
                        s += __shfl_down_sync(0xffffffffu, s, off);
                        q += __shfl_down_sync(0xffffffffu, q, off);
                    }
                    if (!lane) { atomicAdd(&g_sum[nxt][0], s); atomicAdd(&g_sum[nxt][1], q); }
                }
            }
        }
        if (!isLast) gridbar();
    }
}

// ---------------- host launcher ----------------
extern "C" void kernel_launch(void* const* d_in, const int* in_sizes, int n_in,
                              void* d_out, int out_size)
{
    const float* x    = (const float*)d_in[0];
    const float* v1   = (const float*)d_in[1];
    const float* g1   = (const float*)d_in[2];
    const float* b1   = (const float*)d_in[3];
    const float* bn1g = (const float*)d_in[4];
    const float* bn1b = (const float*)d_in[5];
    const float* v2   = (const float*)d_in[6];
    const float* g2   = (const float*)d_in[7];
    const float* b2   = (const float*)d_in[8];
    const float* bn2g = (const float*)d_in[9];
    const float* bn2b = (const float*)d_in[10];
    const float* wf   = (const float*)d_in[11];
    const float* bf   = (const float*)d_in[12];
    float* out = (float*)d_out;

    cudaFuncSetAttribute(k_all, cudaFuncAttributeMaxDynamicSharedMemorySize, SMEM_ALL);
    k_all<<<NB, NT, SMEM_ALL>>>(x, v1, g1, b1, bn1g, bn1b, v2, g2, b2,
                                bn2g, bn2b, wf, bf, out);
    (void)in_sizes; (void)n_in; (void)out_size;
}